// round 11
// baseline (speedup 1.0000x reference)
#include <cuda_runtime.h>

// Shapes (fixed by the problem)
#define D_MODEL   1024
#define HEAD_DIM  64
#define NUM_HEADS 16
#define BATCH     8
#define SEQ       4096
#define KSLICES   8

#define NPROD     64            // producer CTAs (phases 1 & 2)
#define NBLOCKS   1152          // total CTAs: all resident in one wave (<=148*8)
#define NUNITS    (BATCH * SEQ) // 32768 output rows to stamp

// Scratch + sync state (allocation-free rule: __device__ globals).
// All counters return to 0 by kernel end -> identical state every replay.
__device__ float g_Vpart[KSLICES * BATCH * HEAD_DIM];
__device__ float g_row[BATCH * D_MODEL];
__device__ int   g_cnt1 = 0;   // phase-1 arrivals (target NPROD)
__device__ int   g_cnt2 = 0;   // phase-2 arrivals (target NPROD)
__device__ int   g_done = 0;   // broadcast completions (target NBLOCKS)

__device__ __forceinline__ void spin_until(volatile int* p, int target) {
    while (*p < target) __nanosleep(200);
}

__global__ __launch_bounds__(256, 8)
void fused_mqa_kernel(const float* __restrict__ value,
                      const float* __restrict__ Wv,
                      const float* __restrict__ bv,
                      const float* __restrict__ Wo,
                      const float* __restrict__ bo,
                      float4* __restrict__ out) {
    const int bid = blockIdx.x;
    const int t   = threadIdx.x;          // 0..255

    __shared__ float red[4][HEAD_DIM];    // phase 1 reduction
    __shared__ float sV[BATCH * HEAD_DIM];// phase 2 V broadcast

    if (bid < NPROD) {
        // ----- Phase 1: g_row = bo reset + V partials ---------------------
        // 64 CTAs x 256 threads = 16384 threads cover 8192 g_row elements.
        const int gid = bid * 256 + t;
        if (gid < BATCH * D_MODEL)
            g_row[gid] = bo[gid & (D_MODEL - 1)];

        const int ks  = bid & (KSLICES - 1);   // 0..7
        const int b   = bid >> 3;              // 0..7
        const int d   = t & (HEAD_DIM - 1);    // 0..63
        const int sub = t >> 6;                // 0..3
        const int i0  = ks * (D_MODEL / KSLICES) + sub * (D_MODEL / KSLICES / 4);
        const float* vrow = value + b * D_MODEL;

        float acc = 0.f;
        #pragma unroll 8
        for (int i = 0; i < D_MODEL / KSLICES / 4; ++i) {   // 32 iters
            const int ii = i0 + i;
            acc += vrow[ii] * Wv[ii * HEAD_DIM + d];
        }
        red[sub][d] = acc;
        __syncthreads();
        if (sub == 0) {
            g_Vpart[(ks * BATCH + b) * HEAD_DIM + d] =
                red[0][d] + red[1][d] + red[2][d] + red[3][d];
        }
        __syncthreads();
        if (t == 0) { __threadfence(); atomicAdd(&g_cnt1, 1); }

        // ----- Gate 1: all V partials + g_row resets visible --------------
        if (t == 0) { spin_until(&g_cnt1, NPROD); __threadfence(); }
        __syncthreads();

        // ----- Phase 2: row partials (Wo read exactly once) ---------------
        const int j = (bid & 3) * 256 + t;     // 0..1023
        const int h = bid >> 2;                // 0..15

        #pragma unroll
        for (int e = t; e < BATCH * HEAD_DIM; e += 256) {
            const int d2 = e & (HEAD_DIM - 1);
            float s = bv[d2];
            #pragma unroll
            for (int kk = 0; kk < KSLICES; ++kk)
                s += g_Vpart[kk * BATCH * HEAD_DIM + e];
            sV[e] = s;
        }
        __syncthreads();

        float accb[BATCH];
        #pragma unroll
        for (int b2 = 0; b2 < BATCH; ++b2) accb[b2] = 0.f;

        const float* wcol = Wo + (size_t)(h * HEAD_DIM) * D_MODEL + j;
        #pragma unroll 8
        for (int ii = 0; ii < HEAD_DIM; ++ii) {
            const float w = wcol[ii * D_MODEL];         // coalesced
            #pragma unroll
            for (int b2 = 0; b2 < BATCH; ++b2)
                accb[b2] += sV[b2 * HEAD_DIM + ii] * w; // smem broadcast
        }
        #pragma unroll
        for (int b2 = 0; b2 < BATCH; ++b2)
            atomicAdd(&g_row[b2 * D_MODEL + j], accb[b2]);

        __syncthreads();
        if (t == 0) { __threadfence(); atomicAdd(&g_cnt2, 1); }
    }

    // ----- Gate 2: g_row complete (all CTAs wait here) --------------------
    if (t == 0) { spin_until(&g_cnt2, NPROD); __threadfence(); }
    __syncthreads();

    // ----- Phase 3: broadcast out[b,s,:] = row[b,:] (134 MB of stores) ----
    const float4* row4 = reinterpret_cast<const float4*>(g_row);
    for (int u = bid; u < NUNITS; u += NBLOCKS) {
        const int b = u >> 12;              // u / SEQ
        const float4 v = __ldg(&row4[b * (D_MODEL / 4) + t]);
        out[(size_t)u * (D_MODEL / 4) + t] = v;
    }

    // ----- Reset sync state for the next graph replay ---------------------
    __syncthreads();
    if (t == 0) {
        __threadfence();
        const int old = atomicAdd(&g_done, 1);
        if (old == NBLOCKS - 1) {
            g_cnt1 = 0;
            g_cnt2 = 0;
            __threadfence();
            g_done = 0;
        }
    }
}

// ---------------------------------------------------------------------------
// Inputs (metadata order): 0 query, 1 key, 2 value, 3 Wq, 4 bq,
//                          5 Wk, 6 bk, 7 Wv, 8 bv, 9 Wo, 10 bo
// softmax over kv_len=1 is identically 1 -> query/key/Wq/bq/Wk/bk are dead.
// ---------------------------------------------------------------------------
extern "C" void kernel_launch(void* const* d_in, const int* in_sizes, int n_in,
                              void* d_out, int out_size) {
    const float* value = (const float*)d_in[2];
    const float* Wv    = (const float*)d_in[7];
    const float* bv    = (const float*)d_in[8];
    const float* Wo    = (const float*)d_in[9];
    const float* bo    = (const float*)d_in[10];
    float* out = (float*)d_out;

    fused_mqa_kernel<<<NBLOCKS, 256>>>(value, Wv, bv, Wo, bo, (float4*)out);
}

// round 13
// speedup vs baseline: 1.5902x; 1.5902x over previous
#include <cuda_runtime.h>

// Shapes (fixed by the problem)
#define D_MODEL   1024
#define HEAD_DIM  64
#define NUM_HEADS 16
#define BATCH     8
#define SEQ       4096
#define KSLICES   16          // K-split for the V GEMV (phase 1)

#define NPROLOG   128         // prologue CTAs (one per SM, all co-resident)

// Scratch + sync (allocation-free rule: __device__ globals).
// Data buffers fully overwritten each replay; counters reset by last arriver.
__device__ float g_Vpart[KSLICES * BATCH * HEAD_DIM];
__device__ float g_row[BATCH * D_MODEL];
__device__ int   g_cnt1 = 0;   // phase-1 arrivals (target NPROLOG)
__device__ int   g_cnt2 = 0;   // phase-2 arrivals (target NPROLOG)

// ---------------------------------------------------------------------------
// Kernel 1 (fused prologue), grid = 128 CTAs x 256 threads:
//  Phase 1: g_Vpart[ks][b][d] = sum_{i in slice} value[b,i]*Wv[i,d]
//           + distributed g_row[b,j] = bo[j] reset.
//  Gate   : counter barrier across the 128 CTAs (all resident -> safe;
//           __nanosleep back-off so the spin can't pin the scheduler).
//  Phase 2: g_row[b,j] += sum_{ii in half} V[b,ii]*Wo[(h*64+ii)*1024+j]
//           with V folded from partials + bv. Wo (4 MB) read exactly once.
// ---------------------------------------------------------------------------
__global__ __launch_bounds__(256, 1)
void prologue_fused_kernel(const float* __restrict__ value,
                           const float* __restrict__ Wv,
                           const float* __restrict__ bv,
                           const float* __restrict__ Wo,
                           const float* __restrict__ bo) {
    const int bid = blockIdx.x;           // 0..127
    const int t   = threadIdx.x;          // 0..255

    __shared__ float red[4][HEAD_DIM];
    __shared__ float sV[BATCH * HEAD_DIM];

    // ---- Phase 1 ---------------------------------------------------------
    // g_row reset: 128*256 = 32768 threads cover 8192 elements.
    const int gid = bid * 256 + t;
    if (gid < BATCH * D_MODEL)
        g_row[gid] = bo[gid & (D_MODEL - 1)];

    {
        const int ks  = bid & (KSLICES - 1);   // 0..15
        const int b   = bid >> 4;              // 0..7
        const int d   = t & (HEAD_DIM - 1);    // 0..63
        const int sub = t >> 6;                // 0..3
        const int i0  = ks * (D_MODEL / KSLICES) + sub * (D_MODEL / KSLICES / 4);
        const float* vrow = value + b * D_MODEL;

        float acc = 0.f;
        #pragma unroll
        for (int i = 0; i < D_MODEL / KSLICES / 4; ++i) {   // 16 iters, full MLP
            const int ii = i0 + i;
            acc += vrow[ii] * Wv[ii * HEAD_DIM + d];
        }
        red[sub][d] = acc;
        __syncthreads();
        if (sub == 0) {
            g_Vpart[(ks * BATCH + b) * HEAD_DIM + d] =
                red[0][d] + red[1][d] + red[2][d] + red[3][d];
        }
    }
    __syncthreads();
    if (t == 0) { __threadfence(); atomicAdd(&g_cnt1, 1); }

    // ---- Gate (128 CTAs, one per SM -> cannot deadlock) ------------------
    if (t == 0) {
        volatile int* p = &g_cnt1;
        while (*p < NPROLOG) __nanosleep(64);
        __threadfence();
    }
    __syncthreads();

    // ---- Phase 2 ---------------------------------------------------------
    {
        const int j    = (bid & 3) * 256 + t;           // 0..1023
        const int h    = (bid >> 2) & (NUM_HEADS - 1);  // 0..15
        const int half = bid >> 6;                      // 0..1 -> ii split

        #pragma unroll
        for (int e = t; e < BATCH * HEAD_DIM; e += 256) {
            const int d2 = e & (HEAD_DIM - 1);
            float s = bv[d2];
            #pragma unroll
            for (int kk = 0; kk < KSLICES; ++kk)
                s += g_Vpart[kk * BATCH * HEAD_DIM + e];
            sV[e] = s;
        }
        __syncthreads();

        float accb[BATCH];
        #pragma unroll
        for (int b2 = 0; b2 < BATCH; ++b2) accb[b2] = 0.f;

        const int ii0 = half * (HEAD_DIM / 2);
        const float* wcol = Wo + ((size_t)h * HEAD_DIM + ii0) * D_MODEL + j;
        #pragma unroll
        for (int ii = 0; ii < HEAD_DIM / 2; ++ii) {     // 32 coalesced loads
            const float w = wcol[(size_t)ii * D_MODEL];
            const float* vv = sV + ii0 + ii;
            #pragma unroll
            for (int b2 = 0; b2 < BATCH; ++b2)
                accb[b2] += vv[b2 * HEAD_DIM] * w;      // smem broadcast
        }
        #pragma unroll
        for (int b2 = 0; b2 < BATCH; ++b2)
            atomicAdd(&g_row[b2 * D_MODEL + j], accb[b2]);
    }

    // ---- Counter reset for next replay (last arriver) --------------------
    __syncthreads();
    if (t == 0) {
        __threadfence();
        if (atomicAdd(&g_cnt2, 1) == NPROLOG - 1) {
            g_cnt1 = 0;
            __threadfence();
            g_cnt2 = 0;
        }
    }
}

// ---------------------------------------------------------------------------
// Kernel 2: out[b,s,:] = row[b,:]  (134 MB streaming float4 stores; at the
// store-bandwidth floor). Each thread holds one float4 in a register and
// stamps 32 consecutive rows.
// ---------------------------------------------------------------------------
#define S_PER_BLOCK 32
#define ROW_VEC4    (D_MODEL / 4)   // 256

__global__ __launch_bounds__(256, 8)
void broadcast_kernel(float4* __restrict__ out) {
    const int b  = blockIdx.y;
    const int s0 = blockIdx.x * S_PER_BLOCK;
    const int t  = threadIdx.x;

    const float4 v = reinterpret_cast<const float4*>(g_row)[b * ROW_VEC4 + t];

    size_t base = ((size_t)b * SEQ + s0) * ROW_VEC4 + t;
    #pragma unroll
    for (int s = 0; s < S_PER_BLOCK; ++s) {
        out[base + (size_t)s * ROW_VEC4] = v;
    }
}

// ---------------------------------------------------------------------------
// Inputs (metadata order): 0 query, 1 key, 2 value, 3 Wq, 4 bq,
//                          5 Wk, 6 bk, 7 Wv, 8 bv, 9 Wo, 10 bo
// softmax over kv_len=1 is identically 1 -> query/key/Wq/bq/Wk/bk are dead.
// ---------------------------------------------------------------------------
extern "C" void kernel_launch(void* const* d_in, const int* in_sizes, int n_in,
                              void* d_out, int out_size) {
    const float* value = (const float*)d_in[2];
    const float* Wv    = (const float*)d_in[7];
    const float* bv    = (const float*)d_in[8];
    const float* Wo    = (const float*)d_in[9];
    const float* bo    = (const float*)d_in[10];
    float* out = (float*)d_out;

    prologue_fused_kernel<<<NPROLOG, 256>>>(value, Wv, bv, Wo, bo);

    dim3 gridC(SEQ / S_PER_BLOCK, BATCH);
    broadcast_kernel<<<gridC, 256>>>((float4*)out);
}